// round 2
// baseline (speedup 1.0000x reference)
#include <cuda_runtime.h>
#include <cstdint>

// ---------------------------------------------------------------------------
// Problem constants
// ---------------------------------------------------------------------------
#define NHEAD   12
#define HD      64
#define NTOK    512
#define NBATCH  32
#define DIM     768
#define MTOK    (NBATCH * NTOK)        // 16384
#define QKV_N   (3 * DIM)              // 2304
#define ATTN_SCALE 0.125f              // 64^-0.5

// ---------------------------------------------------------------------------
// Scratch (static __device__ arrays -- no allocation allowed)
// ---------------------------------------------------------------------------
__device__ float g_q[(size_t)NBATCH * NHEAD * NTOK * HD];       // 50 MB
__device__ float g_k[(size_t)NBATCH * NHEAD * NTOK * HD];       // 50 MB
__device__ float g_v[(size_t)NBATCH * NHEAD * NTOK * HD];       // 50 MB
__device__ float g_bias[(size_t)NHEAD * NTOK * NTOK];           // 12.6 MB [h][n][m]
__device__ float g_attnout[(size_t)MTOK * DIM];                 // 50 MB

// ---------------------------------------------------------------------------
// Kernel 1: expand relative-position bias table -> g_bias[h][n][m]
// ---------------------------------------------------------------------------
__global__ void bias_gather_kernel(const float* __restrict__ table,
                                   const int*   __restrict__ idx)
{
    int e = blockIdx.x * 256 + threadIdx.x;      // 0 .. 512*512-1
    int id = idx[e];
    const float* t = table + (size_t)id * NHEAD;
#pragma unroll
    for (int h = 0; h < NHEAD; h++)
        g_bias[(size_t)h * NTOK * NTOK + e] = t[h];
}

// ---------------------------------------------------------------------------
// Kernel 2/4: C = A @ B^T + bias.  A [M,K] row-major, Bw [Nn,K] row-major.
// BM=BN=128, BK=16, 256 threads, 8x8 microtile, 16.5 KB static smem.
// MODE 1: A = x, scatter epilogue into g_q/g_k/g_v ([B,H,N,hd], q pre-scaled)
// MODE 0: A = g_attnout, plain epilogue into Cout (final output)
// ---------------------------------------------------------------------------
template <int MODE>
__global__ __launch_bounds__(256, 2)
void gemm_nt_kernel(const float* __restrict__ Ain,
                    const float* __restrict__ Bw,
                    const float* __restrict__ biasv,
                    float* __restrict__ Cout,
                    int M, int Nn, int K)
{
    __shared__ float As[16 * 129];
    __shared__ float Bs[16 * 129];

    const float* A = (MODE == 0) ? g_attnout : Ain;

    const int tid = threadIdx.x;
    const int tx = tid & 15;
    const int ty = tid >> 4;
    const int m0 = blockIdx.y * 128;
    const int n0 = blockIdx.x * 128;

    float acc[8][8];
#pragma unroll
    for (int i = 0; i < 8; i++)
#pragma unroll
        for (int j = 0; j < 8; j++) acc[i][j] = 0.0f;

    for (int kt = 0; kt < K; kt += 16) {
#pragma unroll
        for (int u = 0; u < 2; u++) {
            int f4  = tid * 2 + u;
            int row = f4 >> 2;
            int kc  = (f4 & 3) * 4;
            float4 a = *(const float4*)&A [(size_t)(m0 + row) * K + kt + kc];
            As[(kc + 0) * 129 + row] = a.x;
            As[(kc + 1) * 129 + row] = a.y;
            As[(kc + 2) * 129 + row] = a.z;
            As[(kc + 3) * 129 + row] = a.w;
            float4 b = *(const float4*)&Bw[(size_t)(n0 + row) * K + kt + kc];
            Bs[(kc + 0) * 129 + row] = b.x;
            Bs[(kc + 1) * 129 + row] = b.y;
            Bs[(kc + 2) * 129 + row] = b.z;
            Bs[(kc + 3) * 129 + row] = b.w;
        }
        __syncthreads();

#pragma unroll
        for (int kk = 0; kk < 16; kk++) {
            float a[8], b[8];
#pragma unroll
            for (int i = 0; i < 8; i++)
                a[i] = As[kk * 129 + ty * 8 + i];
#pragma unroll
            for (int j = 0; j < 4; j++) {
                b[j]     = Bs[kk * 129 + tx * 4 + j];
                b[j + 4] = Bs[kk * 129 + 64 + tx * 4 + j];
            }
#pragma unroll
            for (int i = 0; i < 8; i++)
#pragma unroll
                for (int j = 0; j < 8; j++)
                    acc[i][j] = fmaf(a[i], b[j], acc[i][j]);
        }
        __syncthreads();
    }

#pragma unroll
    for (int i = 0; i < 8; i++) {
        int m = m0 + ty * 8 + i;
#pragma unroll
        for (int j = 0; j < 8; j++) {
            int n = n0 + ((j < 4) ? (tx * 4 + j) : (64 + tx * 4 + j - 4));
            float v = acc[i][j] + biasv[n];
            if (MODE == 0) {
                Cout[(size_t)m * Nn + n] = v;
            } else {
                int part = n / DIM;
                int rem  = n - part * DIM;
                int h    = rem >> 6;
                int d    = rem & 63;
                int bb   = m >> 9;
                int tok  = m & 511;
                size_t o = ((size_t)((bb * NHEAD + h) * NTOK + tok)) * HD + d;
                if      (part == 0) g_q[o] = v * ATTN_SCALE;
                else if (part == 1) g_k[o] = v;
                else                g_v[o] = v;
            }
        }
    }
}

// ---------------------------------------------------------------------------
// Kernel 3: fused flash-style attention. Block = 64 query rows x (head,batch).
// 16 chunks of 32 keys, online softmax (running max/sum in smem).
// Static smem ~35 KB -> no cudaFuncSetAttribute needed.
// ---------------------------------------------------------------------------
#define CH 32     // keys per chunk
#define NCHUNK (NTOK / CH)   // 16

__global__ __launch_bounds__(256)
void attn_kernel()
{
    __shared__ float Qt[64 * 64];      // Q transposed: Qt[d][r]
    __shared__ float KV[CH * 64];      // K phase: [c][d]; V phase: [c][d]
    __shared__ float St[CH * 64];      // scores transposed: St[c][r]
    __shared__ float mpart[4 * 64];
    __shared__ float spart[4 * 64];
    __shared__ float m_run[64];
    __shared__ float s_run[64];
    __shared__ float fsc[64];

    const int tid = threadIdx.x;
    const int tx  = tid & 15;          // QK: r-group ; PV: d-group
    const int ty  = tid >> 4;          // QK: c-group ; PV: r-group
    const int row0 = blockIdx.x * 64;
    const int h    = blockIdx.y;
    const int b    = blockIdx.z;
    const size_t base = ((size_t)(b * NHEAD + h)) * NTOK * HD;

    // ---- load Q tile transposed into Qt[d][r] (conflict-free STS) ----
    {
        int r    = tid & 63;
        int dblk = tid >> 6;           // 0..3
#pragma unroll
        for (int u = 0; u < 4; u++) {
            int d4 = dblk * 16 + u * 4;
            float4 q = *(const float4*)&g_q[base + (size_t)(row0 + r) * HD + d4];
            Qt[(d4 + 0) * 64 + r] = q.x;
            Qt[(d4 + 1) * 64 + r] = q.y;
            Qt[(d4 + 2) * 64 + r] = q.z;
            Qt[(d4 + 3) * 64 + r] = q.w;
        }
    }
    if (tid < 64) { m_run[tid] = -1e30f; s_run[tid] = 0.0f; }

    float oacc[4][4];
#pragma unroll
    for (int i = 0; i < 4; i++)
#pragma unroll
        for (int j = 0; j < 4; j++) oacc[i][j] = 0.0f;

    const int rs  = tid & 63;          // stats pass: row
    const int sub = tid >> 6;          // stats pass: column quarter
    const float* brow = &g_bias[((size_t)h * NTOK + row0 + rs) * NTOK];

    for (int ch = 0; ch < NCHUNK; ch++) {
        const int c0 = ch * CH;
        __syncthreads();   // [A] prev PV done with KV; Qt/m_run ready on iter 0

        // ---- load K chunk (coalesced gmem, conflict-free STS.128) ----
#pragma unroll
        for (int u = 0; u < 2; u++) {
            int f  = tid + 256 * u;                 // 0..511
            int c  = f >> 4;
            int d4 = (f & 15) * 4;
            *(float4*)&KV[c * 64 + d4] =
                *(const float4*)&g_k[base + (size_t)(c0 + c) * HD + d4];
        }
        __syncthreads();   // [B]

        // ---- QK^T chunk: St[c][r], c = 2*ty+i, r = 4*tx+j ----
        {
            float sacc[2][4];
#pragma unroll
            for (int i = 0; i < 2; i++)
#pragma unroll
                for (int j = 0; j < 4; j++) sacc[i][j] = 0.0f;

#pragma unroll 8
            for (int d = 0; d < 64; d++) {
                float a0 = KV[(2 * ty + 0) * 64 + d];
                float a1 = KV[(2 * ty + 1) * 64 + d];
                float4 bq = *(const float4*)&Qt[d * 64 + 4 * tx];
                sacc[0][0] = fmaf(a0, bq.x, sacc[0][0]);
                sacc[0][1] = fmaf(a0, bq.y, sacc[0][1]);
                sacc[0][2] = fmaf(a0, bq.z, sacc[0][2]);
                sacc[0][3] = fmaf(a0, bq.w, sacc[0][3]);
                sacc[1][0] = fmaf(a1, bq.x, sacc[1][0]);
                sacc[1][1] = fmaf(a1, bq.y, sacc[1][1]);
                sacc[1][2] = fmaf(a1, bq.z, sacc[1][2]);
                sacc[1][3] = fmaf(a1, bq.w, sacc[1][3]);
            }
#pragma unroll
            for (int i = 0; i < 2; i++)
                *(float4*)&St[(2 * ty + i) * 64 + 4 * tx] =
                    make_float4(sacc[i][0], sacc[i][1], sacc[i][2], sacc[i][3]);
        }
        __syncthreads();   // [C]

        // ---- load V chunk (overwrites KV; QK done reading it) ----
#pragma unroll
        for (int u = 0; u < 2; u++) {
            int f  = tid + 256 * u;
            int c  = f >> 4;
            int d4 = (f & 15) * 4;
            *(float4*)&KV[c * 64 + d4] =
                *(const float4*)&g_v[base + (size_t)(c0 + c) * HD + d4];
        }

        // ---- stage a: bias add + partial row max (conflict-free) ----
        {
            float mp = -1e30f;
#pragma unroll
            for (int cc = 0; cc < 8; cc++) {
                int c = sub * 8 + cc;
                float x = St[c * 64 + rs] + brow[c0 + c];
                St[c * 64 + rs] = x;
                mp = fmaxf(mp, x);
            }
            mpart[sub * 64 + rs] = mp;
        }
        __syncthreads();   // [D]

        if (tid < 64) {
            float m_old = m_run[tid];
            float mc = fmaxf(fmaxf(mpart[tid], mpart[64 + tid]),
                             fmaxf(mpart[128 + tid], mpart[192 + tid]));
            float mn = fmaxf(m_old, mc);
            m_run[tid] = mn;
            fsc[tid] = __expf(m_old - mn);
        }
        __syncthreads();   // [E]

        // ---- stage b: exp in place + partial row sum ----
        {
            float mn = m_run[rs];
            float sp = 0.0f;
#pragma unroll
            for (int cc = 0; cc < 8; cc++) {
                int c = sub * 8 + cc;
                float e = __expf(St[c * 64 + rs] - mn);
                St[c * 64 + rs] = e;
                sp += e;
            }
            spart[sub * 64 + rs] = sp;
        }
        __syncthreads();   // [F]  (also makes V chunk visible)

        if (tid < 64)
            s_run[tid] = s_run[tid] * fsc[tid] +
                         (spart[tid] + spart[64 + tid] +
                          spart[128 + tid] + spart[192 + tid]);

        // ---- P @ V: O[r][d], r = 4*ty+i, d = 4*tx+j ----
        {
            float f0 = fsc[4 * ty + 0];
            float f1 = fsc[4 * ty + 1];
            float f2 = fsc[4 * ty + 2];
            float f3 = fsc[4 * ty + 3];
#pragma unroll
            for (int j = 0; j < 4; j++) {
                oacc[0][j] *= f0; oacc[1][j] *= f1;
                oacc[2][j] *= f2; oacc[3][j] *= f3;
            }
#pragma unroll 8
            for (int kk = 0; kk < CH; kk++) {
                float4 p = *(const float4*)&St[kk * 64 + 4 * ty];
                float4 v = *(const float4*)&KV[kk * 64 + 4 * tx];
                oacc[0][0] = fmaf(p.x, v.x, oacc[0][0]);
                oacc[0][1] = fmaf(p.x, v.y, oacc[0][1]);
                oacc[0][2] = fmaf(p.x, v.z, oacc[0][2]);
                oacc[0][3] = fmaf(p.x, v.w, oacc[0][3]);
                oacc[1][0] = fmaf(p.y, v.x, oacc[1][0]);
                oacc[1][1] = fmaf(p.y, v.y, oacc[1][1]);
                oacc[1][2] = fmaf(p.y, v.z, oacc[1][2]);
                oacc[1][3] = fmaf(p.y, v.w, oacc[1][3]);
                oacc[2][0] = fmaf(p.z, v.x, oacc[2][0]);
                oacc[2][1] = fmaf(p.z, v.y, oacc[2][1]);
                oacc[2][2] = fmaf(p.z, v.z, oacc[2][2]);
                oacc[2][3] = fmaf(p.z, v.w, oacc[2][3]);
                oacc[3][0] = fmaf(p.w, v.x, oacc[3][0]);
                oacc[3][1] = fmaf(p.w, v.y, oacc[3][1]);
                oacc[3][2] = fmaf(p.w, v.z, oacc[3][2]);
                oacc[3][3] = fmaf(p.w, v.w, oacc[3][3]);
            }
        }
    }
    __syncthreads();

    // ---- epilogue: divide by running sum, write [B, N, H*hd] ----
#pragma unroll
    for (int i = 0; i < 4; i++) {
        int r = 4 * ty + i;
        float inv = 1.0f / s_run[r];
        float4 o = make_float4(oacc[i][0] * inv, oacc[i][1] * inv,
                               oacc[i][2] * inv, oacc[i][3] * inv);
        *(float4*)&g_attnout[((size_t)b * NTOK + row0 + r) * DIM + h * HD + 4 * tx] = o;
    }
}

// ---------------------------------------------------------------------------
// Launch (kernel launches only -- fully graph-capturable)
// ---------------------------------------------------------------------------
extern "C" void kernel_launch(void* const* d_in, const int* in_sizes, int n_in,
                              void* d_out, int out_size)
{
    const float* x     = (const float*)d_in[0];
    const float* Wqkv  = (const float*)d_in[1];
    const float* bqkv  = (const float*)d_in[2];
    const float* table = (const float*)d_in[3];
    const int*   idx   = (const int*)  d_in[4];
    const float* Wproj = (const float*)d_in[5];
    const float* bproj = (const float*)d_in[6];
    float* out = (float*)d_out;

    bias_gather_kernel<<<(NTOK * NTOK) / 256, 256>>>(table, idx);

    gemm_nt_kernel<1><<<dim3(QKV_N / 128, MTOK / 128), 256>>>(
        x, Wqkv, bqkv, nullptr, MTOK, QKV_N, DIM);

    attn_kernel<<<dim3(NTOK / 64, NHEAD, NBATCH), 256>>>();

    gemm_nt_kernel<0><<<dim3(DIM / 128, MTOK / 128), 256>>>(
        nullptr, Wproj, bproj, out, MTOK, DIM, DIM);
}

// round 3
// speedup vs baseline: 1.6922x; 1.6922x over previous
#include <cuda_runtime.h>
#include <cstdint>

// ---------------------------------------------------------------------------
// Problem constants
// ---------------------------------------------------------------------------
#define NHEAD   12
#define HD      64
#define NTOK    512
#define NBATCH  32
#define DIM     768
#define MTOK    (NBATCH * NTOK)        // 16384
#define QKV_N   (3 * DIM)              // 2304
#define ATTN_SCALE 0.125f              // 64^-0.5

// ---------------------------------------------------------------------------
// Scratch (static __device__ arrays -- no allocation allowed)
// ---------------------------------------------------------------------------
__device__ float g_q[(size_t)NBATCH * NHEAD * NTOK * HD];
__device__ float g_k[(size_t)NBATCH * NHEAD * NTOK * HD];
__device__ float g_v[(size_t)NBATCH * NHEAD * NTOK * HD];
__device__ float g_bias[(size_t)NHEAD * NTOK * NTOK];           // [h][n][m]
__device__ float g_attnout[(size_t)MTOK * DIM];

// ---------------------------------------------------------------------------
// Helpers: tf32 round + mma.sync m16n8k8 tf32
// ---------------------------------------------------------------------------
__device__ __forceinline__ uint32_t f2tf32(float x) {
    uint32_t r;
    asm("cvt.rna.tf32.f32 %0, %1;" : "=r"(r) : "f"(x));
    return r;
}

__device__ __forceinline__ void mma_tf32(float* c, const uint32_t* a,
                                         const uint32_t* b) {
    asm volatile(
        "mma.sync.aligned.m16n8k8.row.col.f32.tf32.tf32.f32 "
        "{%0,%1,%2,%3}, {%4,%5,%6,%7}, {%8,%9}, {%0,%1,%2,%3};"
        : "+f"(c[0]), "+f"(c[1]), "+f"(c[2]), "+f"(c[3])
        : "r"(a[0]), "r"(a[1]), "r"(a[2]), "r"(a[3]),
          "r"(b[0]), "r"(b[1]));
}

// ---------------------------------------------------------------------------
// Kernel 1: expand relative-position bias table -> g_bias[h][n][m]
// ---------------------------------------------------------------------------
__global__ void bias_gather_kernel(const float* __restrict__ table,
                                   const int*   __restrict__ idx)
{
    int e = blockIdx.x * 256 + threadIdx.x;
    int id = idx[e];
    const float* t = table + (size_t)id * NHEAD;
#pragma unroll
    for (int h = 0; h < NHEAD; h++)
        g_bias[(size_t)h * NTOK * NTOK + e] = t[h];
}

// ---------------------------------------------------------------------------
// Kernel 2/4: TF32 tensor-core GEMM.  C = A @ Bw^T + bias.
// A [M,K] row-major, Bw [Nn,K] row-major. BM=BN=128, BK=32, 256 thr = 8 warps
// (4 m-warps x 2 n-warps, each 32x64). Smem tiles stored fragment-permuted:
//   A frag (m16n8k8): t=(r%8)*4+(k%4), reg=(r%16)/8 + 2*((k%8)/4)
//     As[((mt*4+ks)*32 + t)*4 + reg],  mt=r/16, ks=k/8   -> LDS.128 in loop
//   B frag: t=(n%8)*4+(k%4), reg=(k%8)/4
//     Bs[((nt*4+ks)*32 + t)*2 + reg],  nt=n/8,  ks=k/8   -> LDS.64 in loop
// MODE 1: A = x, scatter epilogue into g_q/g_k/g_v (q pre-scaled)
// MODE 0: A = g_attnout, epilogue -> Cout
// ---------------------------------------------------------------------------
template <int MODE>
__global__ __launch_bounds__(256, 2)
void gemm_tf32_kernel(const float* __restrict__ Ain,
                      const float* __restrict__ Bw,
                      const float* __restrict__ biasv,
                      float* __restrict__ Cout,
                      int M, int Nn, int K)
{
    __shared__ uint32_t As[4096];   // 16 KB
    __shared__ uint32_t Bs[4096];   // 16 KB

    const float* A = (MODE == 0) ? g_attnout : Ain;

    const int tid  = threadIdx.x;
    const int warp = tid >> 5;
    const int lane = tid & 31;
    const int wm   = warp & 3;      // 0..3  -> 32-row slab
    const int wn   = warp >> 2;     // 0..1  -> 64-col slab
    const int m0   = blockIdx.y * 128;
    const int n0   = blockIdx.x * 128;

    float acc[2][8][4];
#pragma unroll
    for (int i = 0; i < 2; i++)
#pragma unroll
        for (int j = 0; j < 8; j++)
#pragma unroll
            for (int r = 0; r < 4; r++) acc[i][j][r] = 0.0f;

    for (int kt = 0; kt < K; kt += 32) {
        // ---- fill permuted tiles (each thread: 4 float4 from A, 4 from Bw) --
#pragma unroll
        for (int u = 0; u < 4; u++) {
            int f4  = tid + 256 * u;          // 0..1023
            int row = f4 >> 3;                // 0..127
            int kq  = f4 & 7;                 // k4-group: k = kq*4
            int ks  = kq >> 1;                // k/8
            int kh  = kq & 1;                 // (k%8)/4

            float4 av = *(const float4*)&A[(size_t)(m0 + row) * K + kt + kq * 4];
            {
                int mt   = row >> 4;
                int r8   = (row >> 3) & 1;
                int reg  = r8 + 2 * kh;
                int base = ((mt * 4 + ks) * 32 + ((row & 7) << 2)) * 4 + reg;
                As[base + 0]  = f2tf32(av.x);
                As[base + 4]  = f2tf32(av.y);
                As[base + 8]  = f2tf32(av.z);
                As[base + 12] = f2tf32(av.w);
            }
            float4 bv = *(const float4*)&Bw[(size_t)(n0 + row) * K + kt + kq * 4];
            {
                int nt   = row >> 3;
                int base = ((nt * 4 + ks) * 32 + ((row & 7) << 2)) * 2 + kh;
                Bs[base + 0] = f2tf32(bv.x);
                Bs[base + 2] = f2tf32(bv.y);
                Bs[base + 4] = f2tf32(bv.z);
                Bs[base + 6] = f2tf32(bv.w);
            }
        }
        __syncthreads();

        // ---- mainloop: 4 k-steps x (2 m-tiles x 8 n-tiles) mma ----
#pragma unroll
        for (int ks = 0; ks < 4; ks++) {
            uint32_t afr[2][4];
#pragma unroll
            for (int mt2 = 0; mt2 < 2; mt2++) {
                int mt = wm * 2 + mt2;
                *(uint4*)afr[mt2] =
                    *(const uint4*)&As[((mt * 4 + ks) * 32 + lane) * 4];
            }
#pragma unroll
            for (int nt2 = 0; nt2 < 8; nt2++) {
                int nt = wn * 8 + nt2;
                uint32_t bfr[2];
                *(uint2*)bfr = *(const uint2*)&Bs[((nt * 4 + ks) * 32 + lane) * 2];
                mma_tf32(acc[0][nt2], afr[0], bfr);
                mma_tf32(acc[1][nt2], afr[1], bfr);
            }
        }
        __syncthreads();
    }

    // ---- epilogue ----
    const int gr = lane >> 2;           // groupID
    const int gl = lane & 3;            // thread in group
#pragma unroll
    for (int mt2 = 0; mt2 < 2; mt2++) {
#pragma unroll
        for (int nt2 = 0; nt2 < 8; nt2++) {
            int n  = n0 + wn * 64 + nt2 * 8 + gl * 2;
            float b0 = biasv[n], b1 = biasv[n + 1];
#pragma unroll
            for (int half = 0; half < 2; half++) {
                int m = m0 + wm * 32 + mt2 * 16 + gr + half * 8;
                float v0 = acc[mt2][nt2][half * 2 + 0] + b0;
                float v1 = acc[mt2][nt2][half * 2 + 1] + b1;
                if (MODE == 0) {
                    *(float2*)&Cout[(size_t)m * Nn + n] = make_float2(v0, v1);
                } else {
                    int part = n / DIM;
                    int rem  = n - part * DIM;
                    int h    = rem >> 6;
                    int d    = rem & 63;
                    int bb   = m >> 9;
                    int tok  = m & 511;
                    size_t o = ((size_t)((bb * NHEAD + h) * NTOK + tok)) * HD + d;
                    if (part == 0) {
                        *(float2*)&g_q[o] =
                            make_float2(v0 * ATTN_SCALE, v1 * ATTN_SCALE);
                    } else if (part == 1) {
                        *(float2*)&g_k[o] = make_float2(v0, v1);
                    } else {
                        *(float2*)&g_v[o] = make_float2(v0, v1);
                    }
                }
            }
        }
    }
}

// ---------------------------------------------------------------------------
// Kernel 3: fused flash-style attention (fp32 SIMT), unchanged from R2.
// ---------------------------------------------------------------------------
#define CH 32
#define NCHUNK (NTOK / CH)

__global__ __launch_bounds__(256)
void attn_kernel()
{
    __shared__ float Qt[64 * 64];
    __shared__ float KV[CH * 64];
    __shared__ float St[CH * 64];
    __shared__ float mpart[4 * 64];
    __shared__ float spart[4 * 64];
    __shared__ float m_run[64];
    __shared__ float s_run[64];
    __shared__ float fsc[64];

    const int tid = threadIdx.x;
    const int tx  = tid & 15;
    const int ty  = tid >> 4;
    const int row0 = blockIdx.x * 64;
    const int h    = blockIdx.y;
    const int b    = blockIdx.z;
    const size_t base = ((size_t)(b * NHEAD + h)) * NTOK * HD;

    {
        int r    = tid & 63;
        int dblk = tid >> 6;
#pragma unroll
        for (int u = 0; u < 4; u++) {
            int d4 = dblk * 16 + u * 4;
            float4 q = *(const float4*)&g_q[base + (size_t)(row0 + r) * HD + d4];
            Qt[(d4 + 0) * 64 + r] = q.x;
            Qt[(d4 + 1) * 64 + r] = q.y;
            Qt[(d4 + 2) * 64 + r] = q.z;
            Qt[(d4 + 3) * 64 + r] = q.w;
        }
    }
    if (tid < 64) { m_run[tid] = -1e30f; s_run[tid] = 0.0f; }

    float oacc[4][4];
#pragma unroll
    for (int i = 0; i < 4; i++)
#pragma unroll
        for (int j = 0; j < 4; j++) oacc[i][j] = 0.0f;

    const int rs  = tid & 63;
    const int sub = tid >> 6;
    const float* brow = &g_bias[((size_t)h * NTOK + row0 + rs) * NTOK];

    for (int ch = 0; ch < NCHUNK; ch++) {
        const int c0 = ch * CH;
        __syncthreads();

#pragma unroll
        for (int u = 0; u < 2; u++) {
            int f  = tid + 256 * u;
            int c  = f >> 4;
            int d4 = (f & 15) * 4;
            *(float4*)&KV[c * 64 + d4] =
                *(const float4*)&g_k[base + (size_t)(c0 + c) * HD + d4];
        }
        __syncthreads();

        {
            float sacc[2][4];
#pragma unroll
            for (int i = 0; i < 2; i++)
#pragma unroll
                for (int j = 0; j < 4; j++) sacc[i][j] = 0.0f;

#pragma unroll 8
            for (int d = 0; d < 64; d++) {
                float a0 = KV[(2 * ty + 0) * 64 + d];
                float a1 = KV[(2 * ty + 1) * 64 + d];
                float4 bq = *(const float4*)&Qt[d * 64 + 4 * tx];
                sacc[0][0] = fmaf(a0, bq.x, sacc[0][0]);
                sacc[0][1] = fmaf(a0, bq.y, sacc[0][1]);
                sacc[0][2] = fmaf(a0, bq.z, sacc[0][2]);
                sacc[0][3] = fmaf(a0, bq.w, sacc[0][3]);
                sacc[1][0] = fmaf(a1, bq.x, sacc[1][0]);
                sacc[1][1] = fmaf(a1, bq.y, sacc[1][1]);
                sacc[1][2] = fmaf(a1, bq.z, sacc[1][2]);
                sacc[1][3] = fmaf(a1, bq.w, sacc[1][3]);
            }
#pragma unroll
            for (int i = 0; i < 2; i++)
                *(float4*)&St[(2 * ty + i) * 64 + 4 * tx] =
                    make_float4(sacc[i][0], sacc[i][1], sacc[i][2], sacc[i][3]);
        }
        __syncthreads();

#pragma unroll
        for (int u = 0; u < 2; u++) {
            int f  = tid + 256 * u;
            int c  = f >> 4;
            int d4 = (f & 15) * 4;
            *(float4*)&KV[c * 64 + d4] =
                *(const float4*)&g_v[base + (size_t)(c0 + c) * HD + d4];
        }

        {
            float mp = -1e30f;
#pragma unroll
            for (int cc = 0; cc < 8; cc++) {
                int c = sub * 8 + cc;
                float x = St[c * 64 + rs] + brow[c0 + c];
                St[c * 64 + rs] = x;
                mp = fmaxf(mp, x);
            }
            mpart[sub * 64 + rs] = mp;
        }
        __syncthreads();

        if (tid < 64) {
            float m_old = m_run[tid];
            float mc = fmaxf(fmaxf(mpart[tid], mpart[64 + tid]),
                             fmaxf(mpart[128 + tid], mpart[192 + tid]));
            float mn = fmaxf(m_old, mc);
            m_run[tid] = mn;
            fsc[tid] = __expf(m_old - mn);
        }
        __syncthreads();

        {
            float mn = m_run[rs];
            float sp = 0.0f;
#pragma unroll
            for (int cc = 0; cc < 8; cc++) {
                int c = sub * 8 + cc;
                float e = __expf(St[c * 64 + rs] - mn);
                St[c * 64 + rs] = e;
                sp += e;
            }
            spart[sub * 64 + rs] = sp;
        }
        __syncthreads();

        if (tid < 64)
            s_run[tid] = s_run[tid] * fsc[tid] +
                         (spart[tid] + spart[64 + tid] +
                          spart[128 + tid] + spart[192 + tid]);

        {
            float f0 = fsc[4 * ty + 0];
            float f1 = fsc[4 * ty + 1];
            float f2 = fsc[4 * ty + 2];
            float f3 = fsc[4 * ty + 3];
#pragma unroll
            for (int j = 0; j < 4; j++) {
                oacc[0][j] *= f0; oacc[1][j] *= f1;
                oacc[2][j] *= f2; oacc[3][j] *= f3;
            }
#pragma unroll 8
            for (int kk = 0; kk < CH; kk++) {
                float4 p = *(const float4*)&St[kk * 64 + 4 * ty];
                float4 v = *(const float4*)&KV[kk * 64 + 4 * tx];
                oacc[0][0] = fmaf(p.x, v.x, oacc[0][0]);
                oacc[0][1] = fmaf(p.x, v.y, oacc[0][1]);
                oacc[0][2] = fmaf(p.x, v.z, oacc[0][2]);
                oacc[0][3] = fmaf(p.x, v.w, oacc[0][3]);
                oacc[1][0] = fmaf(p.y, v.x, oacc[1][0]);
                oacc[1][1] = fmaf(p.y, v.y, oacc[1][1]);
                oacc[1][2] = fmaf(p.y, v.z, oacc[1][2]);
                oacc[1][3] = fmaf(p.y, v.w, oacc[1][3]);
                oacc[2][0] = fmaf(p.z, v.x, oacc[2][0]);
                oacc[2][1] = fmaf(p.z, v.y, oacc[2][1]);
                oacc[2][2] = fmaf(p.z, v.z, oacc[2][2]);
                oacc[2][3] = fmaf(p.z, v.w, oacc[2][3]);
                oacc[3][0] = fmaf(p.w, v.x, oacc[3][0]);
                oacc[3][1] = fmaf(p.w, v.y, oacc[3][1]);
                oacc[3][2] = fmaf(p.w, v.z, oacc[3][2]);
                oacc[3][3] = fmaf(p.w, v.w, oacc[3][3]);
            }
        }
    }
    __syncthreads();

#pragma unroll
    for (int i = 0; i < 4; i++) {
        int r = 4 * ty + i;
        float inv = 1.0f / s_run[r];
        float4 o = make_float4(oacc[i][0] * inv, oacc[i][1] * inv,
                               oacc[i][2] * inv, oacc[i][3] * inv);
        *(float4*)&g_attnout[((size_t)b * NTOK + row0 + r) * DIM + h * HD + 4 * tx] = o;
    }
}

// ---------------------------------------------------------------------------
// Launch (kernel launches only -- fully graph-capturable)
// ---------------------------------------------------------------------------
extern "C" void kernel_launch(void* const* d_in, const int* in_sizes, int n_in,
                              void* d_out, int out_size)
{
    const float* x     = (const float*)d_in[0];
    const float* Wqkv  = (const float*)d_in[1];
    const float* bqkv  = (const float*)d_in[2];
    const float* table = (const float*)d_in[3];
    const int*   idx   = (const int*)  d_in[4];
    const float* Wproj = (const float*)d_in[5];
    const float* bproj = (const float*)d_in[6];
    float* out = (float*)d_out;

    bias_gather_kernel<<<(NTOK * NTOK) / 256, 256>>>(table, idx);

    gemm_tf32_kernel<1><<<dim3(QKV_N / 128, MTOK / 128), 256>>>(
        x, Wqkv, bqkv, nullptr, MTOK, QKV_N, DIM);

    attn_kernel<<<dim3(NTOK / 64, NHEAD, NBATCH), 256>>>();

    gemm_tf32_kernel<0><<<dim3(DIM / 128, MTOK / 128), 256>>>(
        nullptr, Wproj, bproj, out, MTOK, DIM, DIM);
}